// round 1
// baseline (speedup 1.0000x reference)
#include <cuda_runtime.h>
#include <cstdint>

#define B_MAX 65536

// ---------------- device scratch (no allocs allowed) ----------------
__device__ float g_whh [4 * 64 * 64 * 4];   // [l][k][j][gate]
__device__ float g_wih [3 * 64 * 64 * 4];   // [l-1][k][j][gate]
__device__ float g_wih0[3 * 64 * 4];        // [kx][j][gate]
__device__ float g_bias[4 * 64 * 4];        // [l][j][gate]  (b_ih + b_hh)
__device__ float g_init[(size_t)B_MAX * 128]; // [b][128] = (h0 | c0)

typedef unsigned long long ull;

__device__ __forceinline__ ull splat2(float x) {
    ull r; asm("mov.b64 %0, {%1, %1};" : "=l"(r) : "f"(x)); return r;
}
__device__ __forceinline__ ull fma2(ull a, ull b, ull c) {
    ull d; asm("fma.rn.f32x2 %0, %1, %2, %3;" : "=l"(d) : "l"(a), "l"(b), "l"(c)); return d;
}
__device__ __forceinline__ float2 u2f(ull a) {
    float2 f; asm("mov.b64 {%0, %1}, %2;" : "=f"(f.x), "=f"(f.y) : "l"(a)); return f;
}
__device__ __forceinline__ float sigm(float x) {
    return __fdividef(1.f, 1.f + __expf(-x));
}
__device__ __forceinline__ float tanh_(float x) {
    float ax = fabsf(x);
    float e = __expf(-2.f * ax);
    float r = __fdividef(1.f - e, 1.f + e);
    return copysignf(r, x);
}

// ---------------- prologue 1: weight repack ----------------
// W_hh [4][256][64] row-major  -> g_whh [l][k][j][g]
// W_ih_rest [3][256][64]       -> g_wih [lm1][k][j][g]
// W_ih0 [256][3]               -> g_wih0 [kx][j][g]
// b_ih+b_hh [4][256]           -> g_bias [l][j][g]
__global__ void repack_k(const float* __restrict__ W_ih0,
                         const float* __restrict__ W_ih_rest,
                         const float* __restrict__ W_hh,
                         const float* __restrict__ b_ih,
                         const float* __restrict__ b_hh) {
    int idx = blockIdx.x * blockDim.x + threadIdx.x;
    const int N_WHH  = 4 * 256 * 64;
    const int N_WIH  = 3 * 256 * 64;
    const int N_WIH0 = 256 * 3;
    const int N_BIAS = 4 * 256;
    if (idx < N_WHH) {
        int k = idx & 63, row = (idx >> 6) & 255, l = idx >> 14;
        int g = row >> 6, j = row & 63;
        g_whh[(((l * 64 + k) * 64) + j) * 4 + g] = W_hh[idx];
        return;
    }
    idx -= N_WHH;
    if (idx < N_WIH) {
        int k = idx & 63, row = (idx >> 6) & 255, lm1 = idx >> 14;
        int g = row >> 6, j = row & 63;
        g_wih[(((lm1 * 64 + k) * 64) + j) * 4 + g] = W_ih_rest[idx];
        return;
    }
    idx -= N_WIH;
    if (idx < N_WIH0) {
        int row = idx / 3, kx = idx % 3;
        int g = row >> 6, j = row & 63;
        g_wih0[(kx * 64 + j) * 4 + g] = W_ih0[idx];
        return;
    }
    idx -= N_WIH0;
    if (idx < N_BIAS) {
        int l = idx >> 8, row = idx & 255;
        int g = row >> 6, j = row & 63;
        g_bias[(l * 64 + j) * 4 + g] = b_ih[l * 256 + row] + b_hh[l * 256 + row];
    }
}

// ---------------- prologue 2: decoder_fc -> (h0|c0) ----------------
__global__ void embed_k(const float* __restrict__ conds,
                        const float* __restrict__ W1, const float* __restrict__ b1,
                        const float* __restrict__ W2, const float* __restrict__ b2) {
    int b = blockIdx.x;
    __shared__ float hid[64];
    __shared__ float cnd[8];
    int t = threadIdx.x;  // 128 threads
    if (t < 8) cnd[t] = conds[b * 8 + t];
    __syncthreads();
    if (t < 64) {
        float a = b1[t];
        #pragma unroll
        for (int k = 0; k < 8; k++) a += cnd[k] * W1[t * 8 + k];
        hid[t] = fmaxf(a, 0.f);
    }
    __syncthreads();
    float a = b2[t];
    #pragma unroll
    for (int k = 0; k < 64; k++) a += hid[k] * W2[t * 64 + k];
    g_init[(size_t)b * 128 + t] = a;
}

// ---------------- main: 4-layer LSTM, 32 batch / CTA ----------------
// thread layout: j = tid&63 (hidden unit), y = tid>>6 (b-group of 8)
// swizzled h smem: value for batch slot b of row r stored at (b + 8*(r&3)) & 31
#define FMA2_BCAST(A, W, Xa, Xb)            \
    A[0] = fma2(W, Xa.x, A[0]);             \
    A[1] = fma2(W, Xa.y, A[1]);             \
    A[2] = fma2(W, Xb.x, A[2]);             \
    A[3] = fma2(W, Xb.y, A[3]);

__global__ __launch_bounds__(256, 2)
void lstm_main(const float* __restrict__ Wo, const float* __restrict__ bo,
               float* __restrict__ out, int T) {
    __shared__ __align__(16) float h_s[4][64][32];
    __shared__ __align__(16) float x_s[3][32];

    const int tid = threadIdx.x;
    const int j = tid & 63;
    const int y = tid >> 6;
    const int bb0 = blockIdx.x * 32;
    const int bthr = bb0 + y * 8;

    float c0[8], c1[8], c2[8], c3[8];

    // init h/c from embed, x from [0.5, 0.5, 0]
    #pragma unroll
    for (int i = 0; i < 8; i++) {
        const float* gi = g_init + (size_t)(bthr + i) * 128;
        float hv = gi[j];
        float cv = gi[64 + j];
        int pos = ((y * 8 + i) + 8 * (j & 3)) & 31;
        h_s[0][j][pos] = hv; h_s[1][j][pos] = hv;
        h_s[2][j][pos] = hv; h_s[3][j][pos] = hv;
        c0[i] = cv; c1[i] = cv; c2[i] = cv; c3[i] = cv;
    }
    if (tid < 96) {
        int kx = tid >> 5, b = tid & 31;
        x_s[kx][b] = (kx == 2) ? 0.f : 0.5f;
    }
    __syncthreads();

    const float4* WHH = ((const float4*)g_whh) + j;   // + (l*64+k)*64
    const float4* WIH = ((const float4*)g_wih) + j;   // + ((l-1)*64+k)*64
    const float4* BIA = ((const float4*)g_bias) + j;  // + l*64
    const float4* WI0 = ((const float4*)g_wih0) + j;  // + kx*64
    const int base_rb = y * 8;

    for (int t = 0; t < T; t++) {
        #pragma unroll
        for (int l = 0; l < 4; l++) {
            float4 bv = BIA[l * 64];
            ull a0[4], a1[4], a2[4], a3[4];
            {
                ull s0 = splat2(bv.x), s1 = splat2(bv.y), s2 = splat2(bv.z), s3 = splat2(bv.w);
                #pragma unroll
                for (int p = 0; p < 4; p++) { a0[p] = s0; a1[p] = s1; a2[p] = s2; a3[p] = s3; }
            }
            if (l == 0) {
                // input part: x (3 features)
                #pragma unroll
                for (int kx = 0; kx < 3; kx++) {
                    float4 wi = WI0[kx * 64];
                    const ulonglong2* xp = (const ulonglong2*)&x_s[kx][base_rb];
                    ulonglong2 xa = xp[0], xb = xp[1];
                    ull w;
                    w = splat2(wi.x); FMA2_BCAST(a0, w, xa, xb);
                    w = splat2(wi.y); FMA2_BCAST(a1, w, xa, xb);
                    w = splat2(wi.z); FMA2_BCAST(a2, w, xa, xb);
                    w = splat2(wi.w); FMA2_BCAST(a3, w, xa, xb);
                }
                // recurrent part
                #pragma unroll 4
                for (int k = 0; k < 64; k++) {
                    float4 wh = WHH[(0 * 64 + k) * 64];
                    int rb = (base_rb + 8 * (k & 3)) & 31;
                    const ulonglong2* hp = (const ulonglong2*)&h_s[0][k][rb];
                    ulonglong2 ha = hp[0], hb = hp[1];
                    ull w;
                    w = splat2(wh.x); FMA2_BCAST(a0, w, ha, hb);
                    w = splat2(wh.y); FMA2_BCAST(a1, w, ha, hb);
                    w = splat2(wh.z); FMA2_BCAST(a2, w, ha, hb);
                    w = splat2(wh.w); FMA2_BCAST(a3, w, ha, hb);
                }
            } else {
                #pragma unroll 4
                for (int k = 0; k < 64; k++) {
                    float4 wh = WHH[(l * 64 + k) * 64];
                    float4 wi = WIH[((l - 1) * 64 + k) * 64];
                    int rb = (base_rb + 8 * (k & 3)) & 31;
                    const ulonglong2* hp = (const ulonglong2*)&h_s[l][k][rb];
                    const ulonglong2* ip = (const ulonglong2*)&h_s[l - 1][k][rb];
                    ulonglong2 ha = hp[0], hb = hp[1];
                    ulonglong2 xa = ip[0], xb = ip[1];
                    ull w;
                    w = splat2(wh.x); FMA2_BCAST(a0, w, ha, hb);
                    w = splat2(wh.y); FMA2_BCAST(a1, w, ha, hb);
                    w = splat2(wh.z); FMA2_BCAST(a2, w, ha, hb);
                    w = splat2(wh.w); FMA2_BCAST(a3, w, ha, hb);
                    w = splat2(wi.x); FMA2_BCAST(a0, w, xa, xb);
                    w = splat2(wi.y); FMA2_BCAST(a1, w, xa, xb);
                    w = splat2(wi.z); FMA2_BCAST(a2, w, xa, xb);
                    w = splat2(wi.w); FMA2_BCAST(a3, w, xa, xb);
                }
            }
            __syncthreads();  // all reads of h_s[l] / h_s[l-1] done

            const int wbase = (base_rb + 8 * (j & 3)) & 31;
            #define DO_UPDATE(C)                                                        \
            {                                                                           \
                _Pragma("unroll")                                                       \
                for (int p = 0; p < 4; p++) {                                           \
                    float2 iv = u2f(a0[p]), fv = u2f(a1[p]);                            \
                    float2 gv = u2f(a2[p]), ov = u2f(a3[p]);                            \
                    float cn0 = sigm(fv.x) * C[2 * p]     + sigm(iv.x) * tanh_(gv.x);   \
                    float cn1 = sigm(fv.y) * C[2 * p + 1] + sigm(iv.y) * tanh_(gv.y);   \
                    C[2 * p] = cn0; C[2 * p + 1] = cn1;                                 \
                    h_s[l][j][wbase + 2 * p]     = sigm(ov.x) * tanh_(cn0);             \
                    h_s[l][j][wbase + 2 * p + 1] = sigm(ov.y) * tanh_(cn1);             \
                }                                                                       \
            }
            if (l == 0)      DO_UPDATE(c0)
            else if (l == 1) DO_UPDATE(c1)
            else if (l == 2) DO_UPDATE(c2)
            else             DO_UPDATE(c3)
            #undef DO_UPDATE
            __syncthreads();  // h_s[l] visible to next layer
        }

        // pred = h[3] @ Wo.T + bo  (96 threads: (jo, b))
        if (tid < 96) {
            int b = tid & 31, jo = tid >> 5;
            float acc = __ldg(&bo[jo]);
            #pragma unroll 4
            for (int k = 0; k < 64; k++) {
                acc += __ldg(&Wo[jo * 64 + k]) * h_s[3][k][(b + 8 * (k & 3)) & 31];
            }
            x_s[jo][b] = acc;
            out[(size_t)(bb0 + b) * (3 * T) + t * 3 + jo] = acc;
        }
        __syncthreads();  // x_s ready for next step's layer 0
    }
}

// ---------------- entry ----------------
extern "C" void kernel_launch(void* const* d_in, const int* in_sizes, int n_in,
                              void* d_out, int out_size) {
    const float* conds     = (const float*)d_in[0];
    const float* W1        = (const float*)d_in[1];
    const float* b1        = (const float*)d_in[2];
    const float* W2        = (const float*)d_in[3];
    const float* b2        = (const float*)d_in[4];
    const float* W_ih0     = (const float*)d_in[5];
    const float* W_ih_rest = (const float*)d_in[6];
    const float* W_hh      = (const float*)d_in[7];
    const float* b_ih      = (const float*)d_in[8];
    const float* b_hh      = (const float*)d_in[9];
    const float* Wo        = (const float*)d_in[10];
    const float* bo        = (const float*)d_in[11];

    int B = in_sizes[0] / 8;
    if (B > B_MAX) B = B_MAX;
    int T = out_size / (B * 3);

    const int total_repack = 4 * 256 * 64 + 3 * 256 * 64 + 256 * 3 + 4 * 256;
    repack_k<<<(total_repack + 255) / 256, 256>>>(W_ih0, W_ih_rest, W_hh, b_ih, b_hh);
    embed_k<<<B, 128>>>(conds, W1, b1, W2, b2);
    lstm_main<<<B / 32, 256>>>(Wo, bo, (float*)d_out, T);
}